// round 2
// baseline (speedup 1.0000x reference)
#include <cuda_runtime.h>

#define B_    64
#define NPG_  1024
#define K_    20
#define H_    16
#define L_    4
#define N_    (B_ * NPG_)

// ---------------- device scratch (static, no allocation) ----------------
__device__ int   g_nbr[N_ * K_];     // neighbor (src) global indices
__device__ float g_h[N_ * H_];       // node features
__device__ float g_A[N_ * 64];       // per-node precomputed [h@W_hi | h@W_hj]

__device__ __forceinline__ float silu_f(float x) {
    return __fdividef(x, 1.0f + __expf(-x));
}

// ======================= kNN (exact top-20 per node) =======================
// 4 blocks per graph, thread-per-node. Phase 1: value-only top-20 via
// branchless median-insert into a sorted register array. Phase 2: collect
// indices with the exact threshold (ascending j == reference tie-break).
__global__ __launch_bounds__(256) void knn_kernel(const float* __restrict__ pos) {
    __shared__ float sx[NPG_], sy[NPG_], sz[NPG_], sq[NPG_];
    const int graph = blockIdx.x >> 2;
    const int base  = graph * NPG_;
    for (int j = threadIdx.x; j < NPG_; j += 256) {
        float x = pos[(base + j) * 3 + 0];
        float y = pos[(base + j) * 3 + 1];
        float z = pos[(base + j) * 3 + 2];
        sx[j] = x; sy[j] = y; sz[j] = z;
        sq[j] = fmaf(x, x, fmaf(y, y, z * z));
    }
    __syncthreads();

    const int i = ((blockIdx.x & 3) << 8) + threadIdx.x;
    const float xi = sx[i], yi = sy[i], zi = sz[i], sqi = sq[i];

    float a[K_];
#pragma unroll
    for (int s = 0; s < K_; s++) a[s] = 3.4e38f;

    for (int j = 0; j < NPG_; j++) {
        float dot = fmaf(xi, sx[j], fmaf(yi, sy[j], zi * sz[j]));
        float d2  = sqi + sq[j] - 2.0f * dot;
        if (j != i && d2 < a[K_ - 1]) {
            float na[K_];
            na[0] = fminf(a[0], d2);
#pragma unroll
            for (int s = 1; s < K_; s++) na[s] = fminf(fmaxf(d2, a[s - 1]), a[s]);
#pragma unroll
            for (int s = 0; s < K_; s++) a[s] = na[s];
        }
    }

    const float T = a[K_ - 1];
    int cnt = 0;
    const int outb = (base + i) * K_;
    for (int j = 0; j < NPG_; j++) {
        if (cnt >= K_) break;
        float dot = fmaf(xi, sx[j], fmaf(yi, sy[j], zi * sz[j]));
        float d2  = sqi + sq[j] - 2.0f * dot;
        if (j != i && d2 <= T) { g_nbr[outb + cnt] = base + j; cnt++; }
    }
}

// ======================= node embedding ====================================
__global__ __launch_bounds__(256) void embed_kernel(
    const float* __restrict__ pos,
    const float* __restrict__ pw1, const float* __restrict__ pb1,
    const float* __restrict__ pw2, const float* __restrict__ pb2)
{
    __shared__ float w1[48], b1[16], w2[256], b2[16];
    const int tid = threadIdx.x;
    if (tid < 48)  w1[tid] = pw1[tid];
    if (tid < 16)  b1[tid] = pb1[tid];
    for (int q = tid; q < 256; q += 256) w2[q] = pw2[q];
    if (tid >= 32 && tid < 48) b2[tid - 32] = pb2[tid - 32];
    __syncthreads();

    const int n = blockIdx.x * 256 + tid;
    const float p0 = pos[n * 3 + 0], p1 = pos[n * 3 + 1], p2 = pos[n * 3 + 2];

    float t[16];
#pragma unroll
    for (int o = 0; o < 16; o++)
        t[o] = silu_f(fmaf(p2, w1[32 + o], fmaf(p1, w1[16 + o], fmaf(p0, w1[o], b1[o]))));

#pragma unroll
    for (int o = 0; o < 16; o++) {
        float h = b2[o];
#pragma unroll
        for (int q = 0; q < 16; q++) h = fmaf(t[q], w2[q * 16 + o], h);
        g_h[n * 16 + o] = h;
    }
}

// ============ per-layer precompute  A[n] = h[n] @ ew1[l][0:32,:] ===========
__global__ __launch_bounds__(128) void precomp_kernel(const float* __restrict__ ew1, int l) {
    __shared__ float w[1024];
    const int tid = threadIdx.x;
    for (int q = tid; q < 1024; q += 128) w[q] = ew1[l * 1184 + q];
    __syncthreads();

    const int n = blockIdx.x * 128 + tid;
    float h[16];
    const float4* hp = (const float4*)(g_h + n * 16);
#pragma unroll
    for (int q = 0; q < 4; q++) {
        float4 v = hp[q];
        h[q * 4 + 0] = v.x; h[q * 4 + 1] = v.y; h[q * 4 + 2] = v.z; h[q * 4 + 3] = v.w;
    }
#pragma unroll
    for (int o = 0; o < 32; o++) {
        float ai = 0.f, aj = 0.f;
#pragma unroll
        for (int q = 0; q < 16; q++) {
            ai = fmaf(h[q], w[q * 32 + o], ai);
            aj = fmaf(h[q], w[(16 + q) * 32 + o], aj);
        }
        g_A[n * 64 + o]      = ai;
        g_A[n * 64 + 32 + o] = aj;
    }
}

// ======================= fused layer kernel ================================
// 32 nodes/block, 20 threads per node (thread-per-edge), 640 threads.
// smem offsets (floats):
#define SM_WG   0       // 5x32 geo rows of ew1
#define SM_B1   160
#define SM_W2   192     // 32x16
#define SM_B2   704
#define SM_W3   720     // 16x16
#define SM_B3   976
#define SM_N1   992     // 48x32
#define SM_NB1  2528
#define SM_N2   2560    // 32x16
#define SM_NB2  3072
#define SM_OW1  3088    // 16x16
#define SM_OB1  3344
#define SM_OW2  3360    // 16x8
#define SM_OB2  3488
#define SM_OW3  3496    // 8x3
#define SM_OB3  3520
#define SM_M    3536    // 640 x 17 (padded edge messages)
#define SM_CAT  14416   // 32 x 48
#define SM_T1   15952   // 32 x 32
#define SM_HN   16976   // 32 x 16
#define SMEM_FLOATS 17488
#define SMEM_BYTES  (SMEM_FLOATS * 4)

__global__ __launch_bounds__(640) void layer_kernel(
    const float* __restrict__ pos,
    const float* __restrict__ ew1, const float* __restrict__ eb1,
    const float* __restrict__ ew2, const float* __restrict__ eb2,
    const float* __restrict__ ew3, const float* __restrict__ eb3,
    const float* __restrict__ nw1, const float* __restrict__ nb1,
    const float* __restrict__ nw2, const float* __restrict__ nb2,
    const float* __restrict__ ow1, const float* __restrict__ ob1,
    const float* __restrict__ ow2, const float* __restrict__ ob2,
    const float* __restrict__ ow3, const float* __restrict__ ob3,
    float* __restrict__ out, int l, int is_last)
{
    extern __shared__ float S[];
    const int tid = threadIdx.x;

    for (int q = tid; q < 160;  q += 640) S[SM_WG  + q] = ew1[l * 1184 + 1024 + q];
    for (int q = tid; q < 32;   q += 640) S[SM_B1  + q] = eb1[l * 32  + q];
    for (int q = tid; q < 512;  q += 640) S[SM_W2  + q] = ew2[l * 512 + q];
    for (int q = tid; q < 16;   q += 640) S[SM_B2  + q] = eb2[l * 16  + q];
    for (int q = tid; q < 256;  q += 640) S[SM_W3  + q] = ew3[l * 256 + q];
    for (int q = tid; q < 16;   q += 640) S[SM_B3  + q] = eb3[l * 16  + q];
    for (int q = tid; q < 1536; q += 640) S[SM_N1  + q] = nw1[l * 1536 + q];
    for (int q = tid; q < 32;   q += 640) S[SM_NB1 + q] = nb1[l * 32  + q];
    for (int q = tid; q < 512;  q += 640) S[SM_N2  + q] = nw2[l * 512 + q];
    for (int q = tid; q < 16;   q += 640) S[SM_NB2 + q] = nb2[l * 16  + q];
    if (is_last) {
        for (int q = tid; q < 256; q += 640) S[SM_OW1 + q] = ow1[q];
        for (int q = tid; q < 16;  q += 640) S[SM_OB1 + q] = ob1[q];
        for (int q = tid; q < 128; q += 640) S[SM_OW2 + q] = ow2[q];
        for (int q = tid; q < 8;   q += 640) S[SM_OB2 + q] = ob2[q];
        for (int q = tid; q < 24;  q += 640) S[SM_OW3 + q] = ow3[q];
        for (int q = tid; q < 3;   q += 640) S[SM_OB3 + q] = ob3[q];
    }
    __syncthreads();

    // ---------------- edge phase: thread-per-edge ----------------
    const int nl   = tid / 20;
    const int kk   = tid - nl * 20;
    const int node = blockIdx.x * 32 + nl;
    const int src  = g_nbr[node * K_ + kk];

    const float pix = pos[node * 3 + 0], piy = pos[node * 3 + 1], piz = pos[node * 3 + 2];
    const float pjx = pos[src  * 3 + 0], pjy = pos[src  * 3 + 1], pjz = pos[src  * 3 + 2];
    const float rx = pjx - pix, ry = pjy - piy, rz = pjz - piz;
    const float dist = sqrtf(fmaf(rx, rx, fmaf(ry, ry, rz * rz)));
    const float inv  = __fdividef(1.0f, dist + 1e-8f);
    const float ni   = sqrtf(fmaf(pix, pix, fmaf(piy, piy, piz * piz)));
    const float nj   = sqrtf(fmaf(pjx, pjx, fmaf(pjy, pjy, pjz * pjz)));
    const float ii   = __fdividef(1.0f, ni + 1e-8f);
    const float ij   = __fdividef(1.0f, nj + 1e-8f);
    const float dotn = (pix * ii) * (pjx * ij) + (piy * ii) * (pjy * ij) + (piz * ii) * (pjz * ij);
    float geo[5];
    geo[0] = dist; geo[1] = rx * inv; geo[2] = ry * inv; geo[3] = rz * inv; geo[4] = dotn;

    float acc[32];
    const float4* Ai4 = (const float4*)(g_A + node * 64);
    const float4* Aj4 = (const float4*)(g_A + src * 64 + 32);
#pragma unroll
    for (int q = 0; q < 8; q++) {
        float4 a4 = Ai4[q], b4 = Aj4[q];
        acc[q * 4 + 0] = a4.x + b4.x + S[SM_B1 + q * 4 + 0];
        acc[q * 4 + 1] = a4.y + b4.y + S[SM_B1 + q * 4 + 1];
        acc[q * 4 + 2] = a4.z + b4.z + S[SM_B1 + q * 4 + 2];
        acc[q * 4 + 3] = a4.w + b4.w + S[SM_B1 + q * 4 + 3];
    }
#pragma unroll
    for (int g = 0; g < 5; g++) {
        float gv = geo[g];
#pragma unroll
        for (int o = 0; o < 32; o++) acc[o] = fmaf(gv, S[SM_WG + g * 32 + o], acc[o]);
    }
#pragma unroll
    for (int o = 0; o < 32; o++) acc[o] = silu_f(acc[o]);

    float m2[16];
#pragma unroll
    for (int o = 0; o < 16; o++) m2[o] = S[SM_B2 + o];
#pragma unroll
    for (int in = 0; in < 32; in++) {
        float v = acc[in];
#pragma unroll
        for (int o = 0; o < 16; o++) m2[o] = fmaf(v, S[SM_W2 + in * 16 + o], m2[o]);
    }
#pragma unroll
    for (int o = 0; o < 16; o++) m2[o] = silu_f(m2[o]);

    float mv[16];
#pragma unroll
    for (int o = 0; o < 16; o++) mv[o] = S[SM_B3 + o];
#pragma unroll
    for (int in = 0; in < 16; in++) {
        float v = m2[in];
#pragma unroll
        for (int o = 0; o < 16; o++) mv[o] = fmaf(v, S[SM_W3 + in * 16 + o], mv[o]);
    }
#pragma unroll
    for (int d = 0; d < 16; d++) S[SM_M + tid * 17 + d] = mv[d];
    __syncthreads();

    // ---------------- reduce: mean & max over the 20 edges ----------------
    if (tid < 512) {
        const int nn = tid >> 4, d = tid & 15;
        float sum = 0.f, mx = -3.4e38f;
#pragma unroll
        for (int e = 0; e < 20; e++) {
            float v = S[SM_M + (nn * 20 + e) * 17 + d];
            sum += v; mx = fmaxf(mx, v);
        }
        S[SM_CAT + nn * 48 + d]      = g_h[(blockIdx.x * 32 + nn) * 16 + d];
        S[SM_CAT + nn * 48 + 16 + d] = sum * (1.0f / 20.0f);
        S[SM_CAT + nn * 48 + 32 + d] = mx;
    }
    __syncthreads();

    // ---------------- node MLP 1: 48 -> 32 ----------------
    for (int idx = tid; idx < 1024; idx += 640) {
        const int nn = idx >> 5, o = idx & 31;
        float a1 = S[SM_NB1 + o];
#pragma unroll
        for (int q = 0; q < 48; q++) a1 = fmaf(S[SM_CAT + nn * 48 + q], S[SM_N1 + q * 32 + o], a1);
        S[SM_T1 + nn * 32 + o] = silu_f(a1);
    }
    __syncthreads();

    // ---------------- node MLP 2 + residual ----------------
    if (tid < 512) {
        const int nn = tid >> 4, d = tid & 15;
        float u = S[SM_NB2 + d];
#pragma unroll
        for (int q = 0; q < 32; q++) u = fmaf(S[SM_T1 + nn * 32 + q], S[SM_N2 + q * 16 + d], u);
        float hv = S[SM_CAT + nn * 48 + d] + u;
        S[SM_HN + nn * 16 + d] = hv;
        g_h[(blockIdx.x * 32 + nn) * 16 + d] = hv;
    }

    if (!is_last) return;
    __syncthreads();

    // ---------------- output head (last layer only) ----------------
    if (tid < 512) {
        const int nn = tid >> 4, d = tid & 15;
        float a1 = S[SM_OB1 + d];
#pragma unroll
        for (int q = 0; q < 16; q++) a1 = fmaf(S[SM_HN + nn * 16 + q], S[SM_OW1 + q * 16 + d], a1);
        S[SM_T1 + nn * 16 + d] = silu_f(a1);
    }
    __syncthreads();
    if (tid < 256) {
        const int nn = tid >> 3, d = tid & 7;
        float a1 = S[SM_OB2 + d];
#pragma unroll
        for (int q = 0; q < 16; q++) a1 = fmaf(S[SM_T1 + nn * 16 + q], S[SM_OW2 + q * 8 + d], a1);
        S[SM_CAT + nn * 8 + d] = silu_f(a1);
    }
    __syncthreads();
    if (tid < 96) {
        const int nn = tid / 3, d = tid - nn * 3;
        float a1 = S[SM_OB3 + d];
#pragma unroll
        for (int q = 0; q < 8; q++) a1 = fmaf(S[SM_CAT + nn * 8 + q], S[SM_OW3 + q * 3 + d], a1);
        out[(blockIdx.x * 32 + nn) * 3 + d] = a1;
    }
}

// ======================= launch ============================================
extern "C" void kernel_launch(void* const* d_in, const int* in_sizes, int n_in,
                              void* d_out, int out_size) {
    (void)in_sizes; (void)n_in; (void)out_size;
    const float* pos = (const float*)d_in[0];
    const float* pw1 = (const float*)d_in[1];
    const float* pb1 = (const float*)d_in[2];
    const float* pw2 = (const float*)d_in[3];
    const float* pb2 = (const float*)d_in[4];
    const float* ew1 = (const float*)d_in[5];
    const float* eb1 = (const float*)d_in[6];
    const float* ew2 = (const float*)d_in[7];
    const float* eb2 = (const float*)d_in[8];
    const float* ew3 = (const float*)d_in[9];
    const float* eb3 = (const float*)d_in[10];
    const float* nw1 = (const float*)d_in[11];
    const float* nb1 = (const float*)d_in[12];
    const float* nw2 = (const float*)d_in[13];
    const float* nb2 = (const float*)d_in[14];
    const float* ow1 = (const float*)d_in[15];
    const float* ob1 = (const float*)d_in[16];
    const float* ow2 = (const float*)d_in[17];
    const float* ob2 = (const float*)d_in[18];
    const float* ow3 = (const float*)d_in[19];
    const float* ob3 = (const float*)d_in[20];
    float* out = (float*)d_out;

    cudaFuncSetAttribute(layer_kernel, cudaFuncAttributeMaxDynamicSharedMemorySize, SMEM_BYTES);

    knn_kernel<<<N_ / 256, 256>>>(pos);
    embed_kernel<<<N_ / 256, 256>>>(pos, pw1, pb1, pw2, pb2);
    for (int l = 0; l < L_; l++) {
        precomp_kernel<<<N_ / 128, 128>>>(ew1, l);
        layer_kernel<<<N_ / 32, 640, SMEM_BYTES>>>(
            pos, ew1, eb1, ew2, eb2, ew3, eb3,
            nw1, nb1, nw2, nb2,
            ow1, ob1, ow2, ob2, ow3, ob3,
            out, l, (l == L_ - 1) ? 1 : 0);
    }
}

// round 4
// speedup vs baseline: 2.0211x; 2.0211x over previous
#include <cuda_runtime.h>

#define B_    64
#define NPG_  1024
#define K_    20
#define H_    16
#define L_    4
#define N_    (B_ * NPG_)

#define BIGF  3.4e38f

// ---------------- device scratch (static, no allocation) ----------------
__device__ int   g_nbr[N_ * K_];     // neighbor (src) global indices, sorted by distance
__device__ float g_h[N_ * H_];       // node features
__device__ float g_A[N_ * 64];       // per-node precomputed [h@W_hi | h@W_hj]

__device__ __forceinline__ float silu_f(float x) {
    return __fdividef(x, 1.0f + __expf(-x));
}

// Branchless sorted insert with index payload. Descending update uses only
// OLD values of lower slots, so it is correct in-place.
__device__ __forceinline__ void insert20(float (&av)[K_], int (&ai)[K_], float d, int j) {
#pragma unroll
    for (int s = K_ - 1; s >= 1; s--) {
        bool c1 = d < av[s];
        bool c2 = d < av[s - 1];
        float nv = c1 ? (c2 ? av[s - 1] : d) : av[s];
        int   ni = c1 ? (c2 ? ai[s - 1] : j) : ai[s];
        av[s] = nv; ai[s] = ni;
    }
    bool c = d < av[0];
    av[0] = c ? d : av[0];
    ai[0] = c ? j : ai[0];
}

// ======================= kNN (exact top-20 per node) =======================
// Thread-per-node; 4 blocks per graph. Candidates buffered 4-deep per lane,
// flushed (branchless, INF-padded) only when some lane's buffer is full.
__global__ __launch_bounds__(256) void knn_kernel(const float* __restrict__ pos) {
    __shared__ float4 sp[NPG_];
    const int graph = blockIdx.x >> 2;
    const int base  = graph * NPG_;
    for (int j = threadIdx.x; j < NPG_; j += 256) {
        float x = pos[(base + j) * 3 + 0];
        float y = pos[(base + j) * 3 + 1];
        float z = pos[(base + j) * 3 + 2];
        sp[j] = make_float4(x, y, z, fmaf(x, x, fmaf(y, y, z * z)));
    }
    __syncthreads();

    const int il = ((blockIdx.x & 3) << 8) + threadIdx.x;   // graph-local node
    const float4 pi = sp[il];
    const float xi = pi.x, yi = pi.y, zi = pi.z, sqi = pi.w;

    float av[K_]; int ai[K_];
#pragma unroll
    for (int s = 0; s < K_; s++) { av[s] = BIGF; ai[s] = 0; }

    float bd0 = 0, bd1 = 0, bd2 = 0, bd3 = 0;
    int   bj0 = 0, bj1 = 0, bj2 = 0, bj3 = 0;
    int   cnt = 0;

#define KNN_FLUSH() do {                                               \
        float f0 = (cnt > 0) ? bd0 : BIGF;                             \
        float f1 = (cnt > 1) ? bd1 : BIGF;                             \
        float f2 = (cnt > 2) ? bd2 : BIGF;                             \
        float f3 = (cnt > 3) ? bd3 : BIGF;                             \
        insert20(av, ai, f0, bj0);                                     \
        insert20(av, ai, f1, bj1);                                     \
        insert20(av, ai, f2, bj2);                                     \
        insert20(av, ai, f3, bj3);                                     \
        cnt = 0;                                                       \
    } while (0)

    for (int j = 0; j < NPG_; j++) {
        float4 pj = sp[j];
        float dot = fmaf(xi, pj.x, fmaf(yi, pj.y, zi * pj.z));
        float d2  = fmaf(-2.0f, dot, sqi + pj.w);
        d2 = (j == il) ? BIGF : d2;       // self never inserts (strict <)
        bool c = d2 < av[K_ - 1];
        if (c) {
            bd0 = (cnt == 0) ? d2 : bd0;  bj0 = (cnt == 0) ? j : bj0;
            bd1 = (cnt == 1) ? d2 : bd1;  bj1 = (cnt == 1) ? j : bj1;
            bd2 = (cnt == 2) ? d2 : bd2;  bj2 = (cnt == 2) ? j : bj2;
            bd3 = (cnt == 3) ? d2 : bd3;  bj3 = (cnt == 3) ? j : bj3;
            cnt++;
        }
        if (__any_sync(0xffffffffu, cnt >= 4)) KNN_FLUSH();
    }
    KNN_FLUSH();

    const int ob = (base + il) * K_;
#pragma unroll
    for (int s = 0; s < K_; s++) g_nbr[ob + s] = base + ai[s];
}

// ======================= node embedding ====================================
__global__ __launch_bounds__(256) void embed_kernel(
    const float* __restrict__ pos,
    const float* __restrict__ pw1, const float* __restrict__ pb1,
    const float* __restrict__ pw2, const float* __restrict__ pb2)
{
    __shared__ float w1[48], b1[16], w2[256], b2[16];
    const int tid = threadIdx.x;
    if (tid < 48)  w1[tid] = pw1[tid];
    if (tid < 16)  b1[tid] = pb1[tid];
    for (int q = tid; q < 256; q += 256) w2[q] = pw2[q];
    if (tid >= 32 && tid < 48) b2[tid - 32] = pb2[tid - 32];
    __syncthreads();

    const int n = blockIdx.x * 256 + tid;
    const float p0 = pos[n * 3 + 0], p1 = pos[n * 3 + 1], p2 = pos[n * 3 + 2];

    float t[16];
#pragma unroll
    for (int o = 0; o < 16; o++)
        t[o] = silu_f(fmaf(p2, w1[32 + o], fmaf(p1, w1[16 + o], fmaf(p0, w1[o], b1[o]))));

#pragma unroll
    for (int o = 0; o < 16; o++) {
        float h = b2[o];
#pragma unroll
        for (int q = 0; q < 16; q++) h = fmaf(t[q], w2[q * 16 + o], h);
        g_h[n * 16 + o] = h;
    }
}

// ============ per-layer precompute  A[n] = h[n] @ ew1[l][0:32,:] ===========
__global__ __launch_bounds__(128) void precomp_kernel(const float* __restrict__ ew1, int l) {
    __shared__ float w[1024];
    const int tid = threadIdx.x;
    for (int q = tid; q < 1024; q += 128) w[q] = ew1[l * 1184 + q];
    __syncthreads();

    const int n = blockIdx.x * 128 + tid;
    float h[16];
    const float4* hp = (const float4*)(g_h + n * 16);
#pragma unroll
    for (int q = 0; q < 4; q++) {
        float4 v = hp[q];
        h[q * 4 + 0] = v.x; h[q * 4 + 1] = v.y; h[q * 4 + 2] = v.z; h[q * 4 + 3] = v.w;
    }
    float4* Ai = (float4*)(g_A + n * 64);
    float4* Aj = (float4*)(g_A + n * 64 + 32);
#pragma unroll
    for (int og = 0; og < 8; og++) {
        float4 ai = make_float4(0.f, 0.f, 0.f, 0.f);
        float4 aj = make_float4(0.f, 0.f, 0.f, 0.f);
#pragma unroll
        for (int q = 0; q < 16; q++) {
            float hq = h[q];
            float4 wi = *(const float4*)&w[q * 32 + og * 4];
            float4 wj = *(const float4*)&w[(16 + q) * 32 + og * 4];
            ai.x = fmaf(hq, wi.x, ai.x); ai.y = fmaf(hq, wi.y, ai.y);
            ai.z = fmaf(hq, wi.z, ai.z); ai.w = fmaf(hq, wi.w, ai.w);
            aj.x = fmaf(hq, wj.x, aj.x); aj.y = fmaf(hq, wj.y, aj.y);
            aj.z = fmaf(hq, wj.z, aj.z); aj.w = fmaf(hq, wj.w, aj.w);
        }
        Ai[og] = ai; Aj[og] = aj;
    }
}

// ======================= fused layer kernel ================================
// 32 nodes/block, thread-per-edge (640 threads). All weight reads are LDS.128.
#define SM_WG   0       // 5x32 geo rows of ew1
#define SM_B1   160
#define SM_W2   192     // 32x16
#define SM_B2   704
#define SM_W3   720     // 16x16
#define SM_B3   976
#define SM_N1   992     // 48x32
#define SM_NB1  2528
#define SM_N2   2560    // 32x16
#define SM_NB2  3072
#define SM_OW1  3088    // 16x16
#define SM_OB1  3344
#define SM_OW2  3360    // 16x8
#define SM_OB2  3488
#define SM_OW3  3496    // 8x3
#define SM_OB3  3520
#define SM_M    3536    // 640 x 20 (float4-aligned edge messages)
#define SM_CAT  16336   // 32 x 48
#define SM_T1   17872   // 32 x 32
#define SM_HN   18896   // 32 x 16
#define SMEM_FLOATS 19408
#define SMEM_BYTES  (SMEM_FLOATS * 4)

__global__ __launch_bounds__(640, 2) void layer_kernel(
    const float* __restrict__ pos,
    const float* __restrict__ ew1, const float* __restrict__ eb1,
    const float* __restrict__ ew2, const float* __restrict__ eb2,
    const float* __restrict__ ew3, const float* __restrict__ eb3,
    const float* __restrict__ nw1, const float* __restrict__ nb1,
    const float* __restrict__ nw2, const float* __restrict__ nb2,
    const float* __restrict__ ow1, const float* __restrict__ ob1,
    const float* __restrict__ ow2, const float* __restrict__ ob2,
    const float* __restrict__ ow3, const float* __restrict__ ob3,
    float* __restrict__ out, int l, int is_last)
{
    extern __shared__ float S[];
    const float4* S4 = (const float4*)S;
    const int tid = threadIdx.x;

    for (int q = tid; q < 160;  q += 640) S[SM_WG  + q] = ew1[l * 1184 + 1024 + q];
    for (int q = tid; q < 32;   q += 640) S[SM_B1  + q] = eb1[l * 32  + q];
    for (int q = tid; q < 512;  q += 640) S[SM_W2  + q] = ew2[l * 512 + q];
    for (int q = tid; q < 16;   q += 640) S[SM_B2  + q] = eb2[l * 16  + q];
    for (int q = tid; q < 256;  q += 640) S[SM_W3  + q] = ew3[l * 256 + q];
    for (int q = tid; q < 16;   q += 640) S[SM_B3  + q] = eb3[l * 16  + q];
    for (int q = tid; q < 1536; q += 640) S[SM_N1  + q] = nw1[l * 1536 + q];
    for (int q = tid; q < 32;   q += 640) S[SM_NB1 + q] = nb1[l * 32  + q];
    for (int q = tid; q < 512;  q += 640) S[SM_N2  + q] = nw2[l * 512 + q];
    for (int q = tid; q < 16;   q += 640) S[SM_NB2 + q] = nb2[l * 16  + q];
    if (is_last) {
        for (int q = tid; q < 256; q += 640) S[SM_OW1 + q] = ow1[q];
        for (int q = tid; q < 16;  q += 640) S[SM_OB1 + q] = ob1[q];
        for (int q = tid; q < 128; q += 640) S[SM_OW2 + q] = ow2[q];
        for (int q = tid; q < 8;   q += 640) S[SM_OB2 + q] = ob2[q];
        for (int q = tid; q < 24;  q += 640) S[SM_OW3 + q] = ow3[q];
        for (int q = tid; q < 3;   q += 640) S[SM_OB3 + q] = ob3[q];
    }
    __syncthreads();

    // ---------------- edge phase: thread-per-edge ----------------
    {
        const int nl   = tid / 20;
        const int kk   = tid - nl * 20;
        const int node = blockIdx.x * 32 + nl;
        const int src  = g_nbr[node * K_ + kk];

        const float pix = pos[node * 3 + 0], piy = pos[node * 3 + 1], piz = pos[node * 3 + 2];
        const float pjx = pos[src  * 3 + 0], pjy = pos[src  * 3 + 1], pjz = pos[src  * 3 + 2];
        const float rx = pjx - pix, ry = pjy - piy, rz = pjz - piz;
        const float dist = sqrtf(fmaf(rx, rx, fmaf(ry, ry, rz * rz)));
        const float inv  = __fdividef(1.0f, dist + 1e-8f);
        const float ni2  = sqrtf(fmaf(pix, pix, fmaf(piy, piy, piz * piz)));
        const float nj2  = sqrtf(fmaf(pjx, pjx, fmaf(pjy, pjy, pjz * pjz)));
        const float ii   = __fdividef(1.0f, ni2 + 1e-8f);
        const float ij   = __fdividef(1.0f, nj2 + 1e-8f);
        const float dotn = (pix * ii) * (pjx * ij) + (piy * ii) * (pjy * ij) + (piz * ii) * (pjz * ij);
        float geo[5];
        geo[0] = dist; geo[1] = rx * inv; geo[2] = ry * inv; geo[3] = rz * inv; geo[4] = dotn;

        float m2[16];
#pragma unroll
        for (int q = 0; q < 4; q++) {
            float4 b = S4[SM_B2 / 4 + q];
            m2[q * 4 + 0] = b.x; m2[q * 4 + 1] = b.y; m2[q * 4 + 2] = b.z; m2[q * 4 + 3] = b.w;
        }

        // two chunks of 16 layer-1 outputs: keeps live registers ~50
#pragma unroll
        for (int c = 0; c < 2; c++) {
            float acc[16];
            const float4* Ai4 = (const float4*)(g_A + node * 64 + c * 16);
            const float4* Aj4 = (const float4*)(g_A + src * 64 + 32 + c * 16);
#pragma unroll
            for (int q = 0; q < 4; q++) {
                float4 a4 = Ai4[q], b4 = Aj4[q];
                float4 bb = S4[SM_B1 / 4 + c * 4 + q];
                acc[q * 4 + 0] = a4.x + b4.x + bb.x;
                acc[q * 4 + 1] = a4.y + b4.y + bb.y;
                acc[q * 4 + 2] = a4.z + b4.z + bb.z;
                acc[q * 4 + 3] = a4.w + b4.w + bb.w;
            }
#pragma unroll
            for (int g = 0; g < 5; g++) {
                float gv = geo[g];
#pragma unroll
                for (int q = 0; q < 4; q++) {
                    float4 w = S4[SM_WG / 4 + g * 8 + c * 4 + q];
                    acc[q * 4 + 0] = fmaf(gv, w.x, acc[q * 4 + 0]);
                    acc[q * 4 + 1] = fmaf(gv, w.y, acc[q * 4 + 1]);
                    acc[q * 4 + 2] = fmaf(gv, w.z, acc[q * 4 + 2]);
                    acc[q * 4 + 3] = fmaf(gv, w.w, acc[q * 4 + 3]);
                }
            }
#pragma unroll
            for (int o = 0; o < 16; o++) acc[o] = silu_f(acc[o]);
#pragma unroll
            for (int in = 0; in < 16; in++) {
                float v = acc[in];
                int row = c * 16 + in;
#pragma unroll
                for (int q = 0; q < 4; q++) {
                    float4 w = S4[SM_W2 / 4 + row * 4 + q];
                    m2[q * 4 + 0] = fmaf(v, w.x, m2[q * 4 + 0]);
                    m2[q * 4 + 1] = fmaf(v, w.y, m2[q * 4 + 1]);
                    m2[q * 4 + 2] = fmaf(v, w.z, m2[q * 4 + 2]);
                    m2[q * 4 + 3] = fmaf(v, w.w, m2[q * 4 + 3]);
                }
            }
        }
#pragma unroll
        for (int o = 0; o < 16; o++) m2[o] = silu_f(m2[o]);

        float mv[16];
#pragma unroll
        for (int q = 0; q < 4; q++) {
            float4 b = S4[SM_B3 / 4 + q];
            mv[q * 4 + 0] = b.x; mv[q * 4 + 1] = b.y; mv[q * 4 + 2] = b.z; mv[q * 4 + 3] = b.w;
        }
#pragma unroll
        for (int in = 0; in < 16; in++) {
            float v = m2[in];
#pragma unroll
            for (int q = 0; q < 4; q++) {
                float4 w = S4[SM_W3 / 4 + in * 4 + q];
                mv[q * 4 + 0] = fmaf(v, w.x, mv[q * 4 + 0]);
                mv[q * 4 + 1] = fmaf(v, w.y, mv[q * 4 + 1]);
                mv[q * 4 + 2] = fmaf(v, w.z, mv[q * 4 + 2]);
                mv[q * 4 + 3] = fmaf(v, w.w, mv[q * 4 + 3]);
            }
        }
        float4* Mst = (float4*)(S + SM_M + tid * 20);
#pragma unroll
        for (int q = 0; q < 4; q++)
            Mst[q] = make_float4(mv[q * 4 + 0], mv[q * 4 + 1], mv[q * 4 + 2], mv[q * 4 + 3]);
    }
    __syncthreads();

    // ---------------- reduce: mean & max over 20 edges (vectorized) --------
    if (tid < 128) {
        const int nn = tid >> 2, d4 = tid & 3;
        float4 sum = make_float4(0.f, 0.f, 0.f, 0.f);
        float4 mx  = make_float4(-BIGF, -BIGF, -BIGF, -BIGF);
#pragma unroll
        for (int e = 0; e < 20; e++) {
            float4 v = *(const float4*)(S + SM_M + (nn * 20 + e) * 20 + d4 * 4);
            sum.x += v.x; sum.y += v.y; sum.z += v.z; sum.w += v.w;
            mx.x = fmaxf(mx.x, v.x); mx.y = fmaxf(mx.y, v.y);
            mx.z = fmaxf(mx.z, v.z); mx.w = fmaxf(mx.w, v.w);
        }
        float4 hv = *(const float4*)(g_h + (blockIdx.x * 32 + nn) * 16 + d4 * 4);
        *(float4*)(S + SM_CAT + nn * 48 + d4 * 4)      = hv;
        *(float4*)(S + SM_CAT + nn * 48 + 16 + d4 * 4) =
            make_float4(sum.x * 0.05f, sum.y * 0.05f, sum.z * 0.05f, sum.w * 0.05f);
        *(float4*)(S + SM_CAT + nn * 48 + 32 + d4 * 4) = mx;
    }
    __syncthreads();

    // ---------------- node MLP 1: 48 -> 32 (4 outputs per thread) ----------
    if (tid < 256) {
        const int nn = tid >> 3, o4 = tid & 7;
        float4 a = *(const float4*)(S + SM_NB1 + o4 * 4);
#pragma unroll
        for (int q = 0; q < 48; q++) {
            float cv = S[SM_CAT + nn * 48 + q];
            float4 w = S4[(SM_N1 + q * 32 + o4 * 4) >> 2];
            a.x = fmaf(cv, w.x, a.x); a.y = fmaf(cv, w.y, a.y);
            a.z = fmaf(cv, w.z, a.z); a.w = fmaf(cv, w.w, a.w);
        }
        *(float4*)(S + SM_T1 + nn * 32 + o4 * 4) =
            make_float4(silu_f(a.x), silu_f(a.y), silu_f(a.z), silu_f(a.w));
    }
    __syncthreads();

    // ---------------- node MLP 2 + residual (4 outputs per thread) ---------
    if (tid < 128) {
        const int nn = tid >> 2, dg = tid & 3;
        float4 a = *(const float4*)(S + SM_NB2 + dg * 4);
#pragma unroll
        for (int q = 0; q < 32; q++) {
            float tv = S[SM_T1 + nn * 32 + q];
            float4 w = S4[(SM_N2 + q * 16 + dg * 4) >> 2];
            a.x = fmaf(tv, w.x, a.x); a.y = fmaf(tv, w.y, a.y);
            a.z = fmaf(tv, w.z, a.z); a.w = fmaf(tv, w.w, a.w);
        }
        float4 h0 = *(const float4*)(S + SM_CAT + nn * 48 + dg * 4);
        float4 hv = make_float4(h0.x + a.x, h0.y + a.y, h0.z + a.z, h0.w + a.w);
        *(float4*)(S + SM_HN + nn * 16 + dg * 4) = hv;
        *(float4*)(g_h + (blockIdx.x * 32 + nn) * 16 + dg * 4) = hv;
    }

    if (!is_last) return;
    __syncthreads();

    // ---------------- output head (last layer only) ----------------
    if (tid < 512) {
        const int nn = tid >> 4, d = tid & 15;
        float a1 = S[SM_OB1 + d];
#pragma unroll
        for (int q = 0; q < 16; q++) a1 = fmaf(S[SM_HN + nn * 16 + q], S[SM_OW1 + q * 16 + d], a1);
        S[SM_T1 + nn * 16 + d] = silu_f(a1);
    }
    __syncthreads();
    if (tid < 256) {
        const int nn = tid >> 3, d = tid & 7;
        float a1 = S[SM_OB2 + d];
#pragma unroll
        for (int q = 0; q < 16; q++) a1 = fmaf(S[SM_T1 + nn * 16 + q], S[SM_OW2 + q * 8 + d], a1);
        S[SM_CAT + nn * 8 + d] = silu_f(a1);
    }
    __syncthreads();
    if (tid < 96) {
        const int nn = tid / 3, d = tid - nn * 3;
        float a1 = S[SM_OB3 + d];
#pragma unroll
        for (int q = 0; q < 8; q++) a1 = fmaf(S[SM_CAT + nn * 8 + q], S[SM_OW3 + q * 3 + d], a1);
        out[(blockIdx.x * 32 + nn) * 3 + d] = a1;
    }
}

// ======================= launch ============================================
extern "C" void kernel_launch(void* const* d_in, const int* in_sizes, int n_in,
                              void* d_out, int out_size) {
    (void)in_sizes; (void)n_in; (void)out_size;
    const float* pos = (const float*)d_in[0];
    const float* pw1 = (const float*)d_in[1];
    const float* pb1 = (const float*)d_in[2];
    const float* pw2 = (const float*)d_in[3];
    const float* pb2 = (const float*)d_in[4];
    const float* ew1 = (const float*)d_in[5];
    const float* eb1 = (const float*)d_in[6];
    const float* ew2 = (const float*)d_in[7];
    const float* eb2 = (const float*)d_in[8];
    const float* ew3 = (const float*)d_in[9];
    const float* eb3 = (const float*)d_in[10];
    const float* nw1 = (const float*)d_in[11];
    const float* nb1 = (const float*)d_in[12];
    const float* nw2 = (const float*)d_in[13];
    const float* nb2 = (const float*)d_in[14];
    const float* ow1 = (const float*)d_in[15];
    const float* ob1 = (const float*)d_in[16];
    const float* ow2 = (const float*)d_in[17];
    const float* ob2 = (const float*)d_in[18];
    const float* ow3 = (const float*)d_in[19];
    const float* ob3 = (const float*)d_in[20];
    float* out = (float*)d_out;

    cudaFuncSetAttribute(layer_kernel, cudaFuncAttributeMaxDynamicSharedMemorySize, SMEM_BYTES);

    knn_kernel<<<N_ / 256, 256>>>(pos);
    embed_kernel<<<N_ / 256, 256>>>(pos, pw1, pb1, pw2, pb2);
    for (int l = 0; l < L_; l++) {
        precomp_kernel<<<N_ / 128, 128>>>(ew1, l);
        layer_kernel<<<N_ / 32, 640, SMEM_BYTES>>>(
            pos, ew1, eb1, ew2, eb2, ew3, eb3,
            nw1, nb1, nw2, nb2,
            ow1, ob1, ow2, ob2, ow3, ob3,
            out, l, (l == L_ - 1) ? 1 : 0);
    }
}

// round 5
// speedup vs baseline: 2.2589x; 1.1176x over previous
#include <cuda_runtime.h>

#define B_    64
#define NPG_  1024
#define K_    20
#define H_    16
#define L_    4
#define N_    (B_ * NPG_)

#define BIGF  3.4e38f

// ---------------- device scratch (static, no allocation) ----------------
__device__ int   g_nbr[N_ * K_];     // neighbor (src) global indices, sorted by distance
__device__ float g_h[N_ * H_];       // node features
__device__ float g_A[N_ * 64];       // per-node precomputed [h@W_hi | h@W_hj]

__device__ __forceinline__ float silu_f(float x) {
    return __fdividef(x, 1.0f + __expf(-x));
}

// Branchless sorted insert with index payload.
__device__ __forceinline__ void insert20(float (&av)[K_], int (&ai)[K_], float d, int j) {
#pragma unroll
    for (int s = K_ - 1; s >= 1; s--) {
        bool c1 = d < av[s];
        bool c2 = d < av[s - 1];
        float nv = c1 ? (c2 ? av[s - 1] : d) : av[s];
        int   ni = c1 ? (c2 ? ai[s - 1] : j) : ai[s];
        av[s] = nv; ai[s] = ni;
    }
    bool c = d < av[0];
    av[0] = c ? d : av[0];
    ai[0] = c ? j : ai[0];
}

// ======================= kNN (exact top-20 per node) =======================
__global__ __launch_bounds__(256) void knn_kernel(const float* __restrict__ pos) {
    __shared__ float4 sp[NPG_];
    const int graph = blockIdx.x >> 2;
    const int base  = graph * NPG_;
    for (int j = threadIdx.x; j < NPG_; j += 256) {
        float x = pos[(base + j) * 3 + 0];
        float y = pos[(base + j) * 3 + 1];
        float z = pos[(base + j) * 3 + 2];
        sp[j] = make_float4(x, y, z, fmaf(x, x, fmaf(y, y, z * z)));
    }
    __syncthreads();

    const int il = ((blockIdx.x & 3) << 8) + threadIdx.x;
    const float4 pi = sp[il];
    const float xi = pi.x, yi = pi.y, zi = pi.z, sqi = pi.w;

    float av[K_]; int ai[K_];
#pragma unroll
    for (int s = 0; s < K_; s++) { av[s] = BIGF; ai[s] = 0; }

    float bd0 = 0, bd1 = 0, bd2 = 0, bd3 = 0;
    int   bj0 = 0, bj1 = 0, bj2 = 0, bj3 = 0;
    int   cnt = 0;

#define KNN_FLUSH() do {                                               \
        float f0 = (cnt > 0) ? bd0 : BIGF;                             \
        float f1 = (cnt > 1) ? bd1 : BIGF;                             \
        float f2 = (cnt > 2) ? bd2 : BIGF;                             \
        float f3 = (cnt > 3) ? bd3 : BIGF;                             \
        insert20(av, ai, f0, bj0);                                     \
        insert20(av, ai, f1, bj1);                                     \
        insert20(av, ai, f2, bj2);                                     \
        insert20(av, ai, f3, bj3);                                     \
        cnt = 0;                                                       \
    } while (0)

    for (int j = 0; j < NPG_; j++) {
        float4 pj = sp[j];
        float dot = fmaf(xi, pj.x, fmaf(yi, pj.y, zi * pj.z));
        float d2  = fmaf(-2.0f, dot, sqi + pj.w);
        d2 = (j == il) ? BIGF : d2;
        bool c = d2 < av[K_ - 1];
        if (c) {
            bd0 = (cnt == 0) ? d2 : bd0;  bj0 = (cnt == 0) ? j : bj0;
            bd1 = (cnt == 1) ? d2 : bd1;  bj1 = (cnt == 1) ? j : bj1;
            bd2 = (cnt == 2) ? d2 : bd2;  bj2 = (cnt == 2) ? j : bj2;
            bd3 = (cnt == 3) ? d2 : bd3;  bj3 = (cnt == 3) ? j : bj3;
            cnt++;
        }
        if (__any_sync(0xffffffffu, cnt >= 4)) KNN_FLUSH();
    }
    KNN_FLUSH();

    const int ob = (base + il) * K_;
#pragma unroll
    for (int s = 0; s < K_; s++) g_nbr[ob + s] = base + ai[s];
}

// ======================= node embedding ====================================
__global__ __launch_bounds__(256) void embed_kernel(
    const float* __restrict__ pos,
    const float* __restrict__ pw1, const float* __restrict__ pb1,
    const float* __restrict__ pw2, const float* __restrict__ pb2)
{
    __shared__ float w1[48], b1[16], w2[256], b2[16];
    const int tid = threadIdx.x;
    if (tid < 48)  w1[tid] = pw1[tid];
    if (tid < 16)  b1[tid] = pb1[tid];
    for (int q = tid; q < 256; q += 256) w2[q] = pw2[q];
    if (tid >= 32 && tid < 48) b2[tid - 32] = pb2[tid - 32];
    __syncthreads();

    const int n = blockIdx.x * 256 + tid;
    const float p0 = pos[n * 3 + 0], p1 = pos[n * 3 + 1], p2 = pos[n * 3 + 2];

    float t[16];
#pragma unroll
    for (int o = 0; o < 16; o++)
        t[o] = silu_f(fmaf(p2, w1[32 + o], fmaf(p1, w1[16 + o], fmaf(p0, w1[o], b1[o]))));

#pragma unroll
    for (int o = 0; o < 16; o++) {
        float h = b2[o];
#pragma unroll
        for (int q = 0; q < 16; q++) h = fmaf(t[q], w2[q * 16 + o], h);
        g_h[n * 16 + o] = h;
    }
}

// ============ per-layer precompute  A[n] = h[n] @ ew1[l][0:32,:] ===========
__global__ __launch_bounds__(128) void precomp_kernel(const float* __restrict__ ew1, int l) {
    __shared__ float w[1024];
    const int tid = threadIdx.x;
    for (int q = tid; q < 1024; q += 128) w[q] = ew1[l * 1184 + q];
    __syncthreads();

    const int n = blockIdx.x * 128 + tid;
    float h[16];
    const float4* hp = (const float4*)(g_h + n * 16);
#pragma unroll
    for (int q = 0; q < 4; q++) {
        float4 v = hp[q];
        h[q * 4 + 0] = v.x; h[q * 4 + 1] = v.y; h[q * 4 + 2] = v.z; h[q * 4 + 3] = v.w;
    }
    float4* Ai = (float4*)(g_A + n * 64);
    float4* Aj = (float4*)(g_A + n * 64 + 32);
#pragma unroll
    for (int og = 0; og < 8; og++) {
        float4 ai = make_float4(0.f, 0.f, 0.f, 0.f);
        float4 aj = make_float4(0.f, 0.f, 0.f, 0.f);
#pragma unroll
        for (int q = 0; q < 16; q++) {
            float hq = h[q];
            float4 wi = *(const float4*)&w[q * 32 + og * 4];
            float4 wj = *(const float4*)&w[(16 + q) * 32 + og * 4];
            ai.x = fmaf(hq, wi.x, ai.x); ai.y = fmaf(hq, wi.y, ai.y);
            ai.z = fmaf(hq, wi.z, ai.z); ai.w = fmaf(hq, wi.w, ai.w);
            aj.x = fmaf(hq, wj.x, aj.x); aj.y = fmaf(hq, wj.y, aj.y);
            aj.z = fmaf(hq, wj.z, aj.z); aj.w = fmaf(hq, wj.w, aj.w);
        }
        Ai[og] = ai; Aj[og] = aj;
    }
}

// ======================= fused layer kernel ================================
// 32 nodes/block, 320 threads, TWO edges per thread (k and k+10) so every
// weight LDS.128 feeds FMAs for two edges. 2 blocks/SM.
#define SM_WG   0       // 5x32 geo rows of ew1
#define SM_B1   160
#define SM_W2   192     // 32x16
#define SM_B2   704
#define SM_W3   720     // 16x16
#define SM_B3   976
#define SM_N1   992     // 48x32
#define SM_NB1  2528
#define SM_N2   2560    // 32x16
#define SM_NB2  3072
#define SM_OW1  3088    // 16x16
#define SM_OB1  3344
#define SM_OW2  3360    // 16x8
#define SM_OB2  3488
#define SM_OW3  3496    // 8x3
#define SM_OB3  3520
#define SM_M    3536    // 32 nodes x 20 edges x 20 floats (16 used + pad)
#define SM_CAT  16336   // 32 x 48
#define SM_T1   17872   // 32 x 32
#define SM_HN   18896   // 32 x 16
#define SMEM_FLOATS 19408
#define SMEM_BYTES  (SMEM_FLOATS * 4)

__global__ __launch_bounds__(320, 2) void layer_kernel(
    const float* __restrict__ pos,
    const float* __restrict__ ew1, const float* __restrict__ eb1,
    const float* __restrict__ ew2, const float* __restrict__ eb2,
    const float* __restrict__ ew3, const float* __restrict__ eb3,
    const float* __restrict__ nw1, const float* __restrict__ nb1,
    const float* __restrict__ nw2, const float* __restrict__ nb2,
    const float* __restrict__ ow1, const float* __restrict__ ob1,
    const float* __restrict__ ow2, const float* __restrict__ ob2,
    const float* __restrict__ ow3, const float* __restrict__ ob3,
    float* __restrict__ out, int l, int is_last)
{
    extern __shared__ float S[];
    const float4* S4 = (const float4*)S;
    const int tid = threadIdx.x;

    for (int q = tid; q < 160;  q += 320) S[SM_WG  + q] = ew1[l * 1184 + 1024 + q];
    for (int q = tid; q < 32;   q += 320) S[SM_B1  + q] = eb1[l * 32  + q];
    for (int q = tid; q < 512;  q += 320) S[SM_W2  + q] = ew2[l * 512 + q];
    for (int q = tid; q < 16;   q += 320) S[SM_B2  + q] = eb2[l * 16  + q];
    for (int q = tid; q < 256;  q += 320) S[SM_W3  + q] = ew3[l * 256 + q];
    for (int q = tid; q < 16;   q += 320) S[SM_B3  + q] = eb3[l * 16  + q];
    for (int q = tid; q < 1536; q += 320) S[SM_N1  + q] = nw1[l * 1536 + q];
    for (int q = tid; q < 32;   q += 320) S[SM_NB1 + q] = nb1[l * 32  + q];
    for (int q = tid; q < 512;  q += 320) S[SM_N2  + q] = nw2[l * 512 + q];
    for (int q = tid; q < 16;   q += 320) S[SM_NB2 + q] = nb2[l * 16  + q];
    if (is_last) {
        for (int q = tid; q < 256; q += 320) S[SM_OW1 + q] = ow1[q];
        for (int q = tid; q < 16;  q += 320) S[SM_OB1 + q] = ob1[q];
        for (int q = tid; q < 128; q += 320) S[SM_OW2 + q] = ow2[q];
        for (int q = tid; q < 8;   q += 320) S[SM_OB2 + q] = ob2[q];
        for (int q = tid; q < 24;  q += 320) S[SM_OW3 + q] = ow3[q];
        for (int q = tid; q < 3;   q += 320) S[SM_OB3 + q] = ob3[q];
    }
    __syncthreads();

    // ---------------- edge phase: two edges per thread ----------------
    {
        const int nl   = tid / 10;              // node-local index, 0..31
        const int k0   = tid - nl * 10;         // first edge slot (second is k0+10)
        const int node = blockIdx.x * 32 + nl;
        const int src0 = g_nbr[node * K_ + k0];
        const int src1 = g_nbr[node * K_ + k0 + 10];

        const float pix = pos[node * 3 + 0], piy = pos[node * 3 + 1], piz = pos[node * 3 + 2];
        const float ni2 = sqrtf(fmaf(pix, pix, fmaf(piy, piy, piz * piz)));
        const float ii  = __fdividef(1.0f, ni2 + 1e-8f);
        const float uix = pix * ii, uiy = piy * ii, uiz = piz * ii;

        float geo0[5], geo1[5];
        {
            const float pjx = pos[src0 * 3 + 0], pjy = pos[src0 * 3 + 1], pjz = pos[src0 * 3 + 2];
            const float rx = pjx - pix, ry = pjy - piy, rz = pjz - piz;
            const float dist = sqrtf(fmaf(rx, rx, fmaf(ry, ry, rz * rz)));
            const float inv  = __fdividef(1.0f, dist + 1e-8f);
            const float nj2  = sqrtf(fmaf(pjx, pjx, fmaf(pjy, pjy, pjz * pjz)));
            const float ij   = __fdividef(1.0f, nj2 + 1e-8f);
            geo0[0] = dist; geo0[1] = rx * inv; geo0[2] = ry * inv; geo0[3] = rz * inv;
            geo0[4] = uix * (pjx * ij) + uiy * (pjy * ij) + uiz * (pjz * ij);
        }
        {
            const float pjx = pos[src1 * 3 + 0], pjy = pos[src1 * 3 + 1], pjz = pos[src1 * 3 + 2];
            const float rx = pjx - pix, ry = pjy - piy, rz = pjz - piz;
            const float dist = sqrtf(fmaf(rx, rx, fmaf(ry, ry, rz * rz)));
            const float inv  = __fdividef(1.0f, dist + 1e-8f);
            const float nj2  = sqrtf(fmaf(pjx, pjx, fmaf(pjy, pjy, pjz * pjz)));
            const float ij   = __fdividef(1.0f, nj2 + 1e-8f);
            geo1[0] = dist; geo1[1] = rx * inv; geo1[2] = ry * inv; geo1[3] = rz * inv;
            geo1[4] = uix * (pjx * ij) + uiy * (pjy * ij) + uiz * (pjz * ij);
        }

        float m20[16], m21[16];
#pragma unroll
        for (int q = 0; q < 4; q++) {
            float4 b = S4[SM_B2 / 4 + q];
            m20[q * 4 + 0] = b.x; m20[q * 4 + 1] = b.y; m20[q * 4 + 2] = b.z; m20[q * 4 + 3] = b.w;
            m21[q * 4 + 0] = b.x; m21[q * 4 + 1] = b.y; m21[q * 4 + 2] = b.z; m21[q * 4 + 3] = b.w;
        }

#pragma unroll
        for (int c = 0; c < 2; c++) {
            float a0[16], a1[16];
            const float4* Ai4  = (const float4*)(g_A + node * 64 + c * 16);
            const float4* Aj40 = (const float4*)(g_A + src0 * 64 + 32 + c * 16);
            const float4* Aj41 = (const float4*)(g_A + src1 * 64 + 32 + c * 16);
#pragma unroll
            for (int q = 0; q < 4; q++) {
                float4 ai = Ai4[q];
                float4 b0 = Aj40[q], b1 = Aj41[q];
                float4 bb = S4[SM_B1 / 4 + c * 4 + q];
                float bx = ai.x + bb.x, by = ai.y + bb.y, bz = ai.z + bb.z, bw = ai.w + bb.w;
                a0[q * 4 + 0] = bx + b0.x; a0[q * 4 + 1] = by + b0.y;
                a0[q * 4 + 2] = bz + b0.z; a0[q * 4 + 3] = bw + b0.w;
                a1[q * 4 + 0] = bx + b1.x; a1[q * 4 + 1] = by + b1.y;
                a1[q * 4 + 2] = bz + b1.z; a1[q * 4 + 3] = bw + b1.w;
            }
#pragma unroll
            for (int g = 0; g < 5; g++) {
                float g0 = geo0[g], g1 = geo1[g];
#pragma unroll
                for (int q = 0; q < 4; q++) {
                    float4 w = S4[SM_WG / 4 + g * 8 + c * 4 + q];
                    a0[q * 4 + 0] = fmaf(g0, w.x, a0[q * 4 + 0]);
                    a0[q * 4 + 1] = fmaf(g0, w.y, a0[q * 4 + 1]);
                    a0[q * 4 + 2] = fmaf(g0, w.z, a0[q * 4 + 2]);
                    a0[q * 4 + 3] = fmaf(g0, w.w, a0[q * 4 + 3]);
                    a1[q * 4 + 0] = fmaf(g1, w.x, a1[q * 4 + 0]);
                    a1[q * 4 + 1] = fmaf(g1, w.y, a1[q * 4 + 1]);
                    a1[q * 4 + 2] = fmaf(g1, w.z, a1[q * 4 + 2]);
                    a1[q * 4 + 3] = fmaf(g1, w.w, a1[q * 4 + 3]);
                }
            }
#pragma unroll
            for (int o = 0; o < 16; o++) { a0[o] = silu_f(a0[o]); a1[o] = silu_f(a1[o]); }
#pragma unroll
            for (int in = 0; in < 16; in++) {
                float v0 = a0[in], v1 = a1[in];
                int row = c * 16 + in;
#pragma unroll
                for (int q = 0; q < 4; q++) {
                    float4 w = S4[SM_W2 / 4 + row * 4 + q];
                    m20[q * 4 + 0] = fmaf(v0, w.x, m20[q * 4 + 0]);
                    m20[q * 4 + 1] = fmaf(v0, w.y, m20[q * 4 + 1]);
                    m20[q * 4 + 2] = fmaf(v0, w.z, m20[q * 4 + 2]);
                    m20[q * 4 + 3] = fmaf(v0, w.w, m20[q * 4 + 3]);
                    m21[q * 4 + 0] = fmaf(v1, w.x, m21[q * 4 + 0]);
                    m21[q * 4 + 1] = fmaf(v1, w.y, m21[q * 4 + 1]);
                    m21[q * 4 + 2] = fmaf(v1, w.z, m21[q * 4 + 2]);
                    m21[q * 4 + 3] = fmaf(v1, w.w, m21[q * 4 + 3]);
                }
            }
        }
#pragma unroll
        for (int o = 0; o < 16; o++) { m20[o] = silu_f(m20[o]); m21[o] = silu_f(m21[o]); }

        float mv0[16], mv1[16];
#pragma unroll
        for (int q = 0; q < 4; q++) {
            float4 b = S4[SM_B3 / 4 + q];
            mv0[q * 4 + 0] = b.x; mv0[q * 4 + 1] = b.y; mv0[q * 4 + 2] = b.z; mv0[q * 4 + 3] = b.w;
            mv1[q * 4 + 0] = b.x; mv1[q * 4 + 1] = b.y; mv1[q * 4 + 2] = b.z; mv1[q * 4 + 3] = b.w;
        }
#pragma unroll
        for (int in = 0; in < 16; in++) {
            float v0 = m20[in], v1 = m21[in];
#pragma unroll
            for (int q = 0; q < 4; q++) {
                float4 w = S4[SM_W3 / 4 + in * 4 + q];
                mv0[q * 4 + 0] = fmaf(v0, w.x, mv0[q * 4 + 0]);
                mv0[q * 4 + 1] = fmaf(v0, w.y, mv0[q * 4 + 1]);
                mv0[q * 4 + 2] = fmaf(v0, w.z, mv0[q * 4 + 2]);
                mv0[q * 4 + 3] = fmaf(v0, w.w, mv0[q * 4 + 3]);
                mv1[q * 4 + 0] = fmaf(v1, w.x, mv1[q * 4 + 0]);
                mv1[q * 4 + 1] = fmaf(v1, w.y, mv1[q * 4 + 1]);
                mv1[q * 4 + 2] = fmaf(v1, w.z, mv1[q * 4 + 2]);
                mv1[q * 4 + 3] = fmaf(v1, w.w, mv1[q * 4 + 3]);
            }
        }
        float4* M0 = (float4*)(S + SM_M + (nl * 20 + k0) * 20);
        float4* M1 = (float4*)(S + SM_M + (nl * 20 + k0 + 10) * 20);
#pragma unroll
        for (int q = 0; q < 4; q++) {
            M0[q] = make_float4(mv0[q * 4 + 0], mv0[q * 4 + 1], mv0[q * 4 + 2], mv0[q * 4 + 3]);
            M1[q] = make_float4(mv1[q * 4 + 0], mv1[q * 4 + 1], mv1[q * 4 + 2], mv1[q * 4 + 3]);
        }
    }
    __syncthreads();

    // ---------------- reduce: mean & max over 20 edges ----------------
    if (tid < 128) {
        const int nn = tid >> 2, d4 = tid & 3;
        float4 sum = make_float4(0.f, 0.f, 0.f, 0.f);
        float4 mx  = make_float4(-BIGF, -BIGF, -BIGF, -BIGF);
#pragma unroll
        for (int e = 0; e < 20; e++) {
            float4 v = *(const float4*)(S + SM_M + (nn * 20 + e) * 20 + d4 * 4);
            sum.x += v.x; sum.y += v.y; sum.z += v.z; sum.w += v.w;
            mx.x = fmaxf(mx.x, v.x); mx.y = fmaxf(mx.y, v.y);
            mx.z = fmaxf(mx.z, v.z); mx.w = fmaxf(mx.w, v.w);
        }
        float4 hv = *(const float4*)(g_h + (blockIdx.x * 32 + nn) * 16 + d4 * 4);
        *(float4*)(S + SM_CAT + nn * 48 + d4 * 4)      = hv;
        *(float4*)(S + SM_CAT + nn * 48 + 16 + d4 * 4) =
            make_float4(sum.x * 0.05f, sum.y * 0.05f, sum.z * 0.05f, sum.w * 0.05f);
        *(float4*)(S + SM_CAT + nn * 48 + 32 + d4 * 4) = mx;
    }
    __syncthreads();

    // ---------------- node MLP 1: 48 -> 32 (4 outputs per thread) ----------
    if (tid < 256) {
        const int nn = tid >> 3, o4 = tid & 7;
        float4 a = *(const float4*)(S + SM_NB1 + o4 * 4);
#pragma unroll
        for (int q = 0; q < 48; q++) {
            float cv = S[SM_CAT + nn * 48 + q];
            float4 w = S4[(SM_N1 + q * 32 + o4 * 4) >> 2];
            a.x = fmaf(cv, w.x, a.x); a.y = fmaf(cv, w.y, a.y);
            a.z = fmaf(cv, w.z, a.z); a.w = fmaf(cv, w.w, a.w);
        }
        *(float4*)(S + SM_T1 + nn * 32 + o4 * 4) =
            make_float4(silu_f(a.x), silu_f(a.y), silu_f(a.z), silu_f(a.w));
    }
    __syncthreads();

    // ---------------- node MLP 2 + residual ----------------
    if (tid < 128) {
        const int nn = tid >> 2, dg = tid & 3;
        float4 a = *(const float4*)(S + SM_NB2 + dg * 4);
#pragma unroll
        for (int q = 0; q < 32; q++) {
            float tv = S[SM_T1 + nn * 32 + q];
            float4 w = S4[(SM_N2 + q * 16 + dg * 4) >> 2];
            a.x = fmaf(tv, w.x, a.x); a.y = fmaf(tv, w.y, a.y);
            a.z = fmaf(tv, w.z, a.z); a.w = fmaf(tv, w.w, a.w);
        }
        float4 h0 = *(const float4*)(S + SM_CAT + nn * 48 + dg * 4);
        float4 hv = make_float4(h0.x + a.x, h0.y + a.y, h0.z + a.z, h0.w + a.w);
        *(float4*)(S + SM_HN + nn * 16 + dg * 4) = hv;
        *(float4*)(g_h + (blockIdx.x * 32 + nn) * 16 + dg * 4) = hv;
    }

    if (!is_last) return;
    __syncthreads();

    // ---------------- output head (last layer only) ----------------
    for (int idx = tid; idx < 512; idx += 320) {
        const int nn = idx >> 4, d = idx & 15;
        float a1 = S[SM_OB1 + d];
#pragma unroll
        for (int q = 0; q < 16; q++) a1 = fmaf(S[SM_HN + nn * 16 + q], S[SM_OW1 + q * 16 + d], a1);
        S[SM_T1 + nn * 16 + d] = silu_f(a1);
    }
    __syncthreads();
    if (tid < 256) {
        const int nn = tid >> 3, d = tid & 7;
        float a1 = S[SM_OB2 + d];
#pragma unroll
        for (int q = 0; q < 16; q++) a1 = fmaf(S[SM_T1 + nn * 16 + q], S[SM_OW2 + q * 8 + d], a1);
        S[SM_CAT + nn * 8 + d] = silu_f(a1);
    }
    __syncthreads();
    if (tid < 96) {
        const int nn = tid / 3, d = tid - nn * 3;
        float a1 = S[SM_OB3 + d];
#pragma unroll
        for (int q = 0; q < 8; q++) a1 = fmaf(S[SM_CAT + nn * 8 + q], S[SM_OW3 + q * 3 + d], a1);
        out[(blockIdx.x * 32 + nn) * 3 + d] = a1;
    }
}

// ======================= launch ============================================
extern "C" void kernel_launch(void* const* d_in, const int* in_sizes, int n_in,
                              void* d_out, int out_size) {
    (void)in_sizes; (void)n_in; (void)out_size;
    const float* pos = (const float*)d_in[0];
    const float* pw1 = (const float*)d_in[1];
    const float* pb1 = (const float*)d_in[2];
    const float* pw2 = (const float*)d_in[3];
    const float* pb2 = (const float*)d_in[4];
    const float* ew1 = (const float*)d_in[5];
    const float* eb1 = (const float*)d_in[6];
    const float* ew2 = (const float*)d_in[7];
    const float* eb2 = (const float*)d_in[8];
    const float* ew3 = (const float*)d_in[9];
    const float* eb3 = (const float*)d_in[10];
    const float* nw1 = (const float*)d_in[11];
    const float* nb1 = (const float*)d_in[12];
    const float* nw2 = (const float*)d_in[13];
    const float* nb2 = (const float*)d_in[14];
    const float* ow1 = (const float*)d_in[15];
    const float* ob1 = (const float*)d_in[16];
    const float* ow2 = (const float*)d_in[17];
    const float* ob2 = (const float*)d_in[18];
    const float* ow3 = (const float*)d_in[19];
    const float* ob3 = (const float*)d_in[20];
    float* out = (float*)d_out;

    cudaFuncSetAttribute(layer_kernel, cudaFuncAttributeMaxDynamicSharedMemorySize, SMEM_BYTES);

    knn_kernel<<<N_ / 256, 256>>>(pos);
    embed_kernel<<<N_ / 256, 256>>>(pos, pw1, pb1, pw2, pb2);
    for (int l = 0; l < L_; l++) {
        precomp_kernel<<<N_ / 128, 128>>>(ew1, l);
        layer_kernel<<<N_ / 32, 320, SMEM_BYTES>>>(
            pos, ew1, eb1, ew2, eb2, ew3, eb3,
            nw1, nb1, nw2, nb2,
            ow1, ob1, ow2, ob2, ow3, ob3,
            out, l, (l == L_ - 1) ? 1 : 0);
    }
}

// round 6
// speedup vs baseline: 2.2711x; 1.0054x over previous
#include <cuda_runtime.h>

#define B_    64
#define NPG_  1024
#define K_    20
#define H_    16
#define L_    4
#define N_    (B_ * NPG_)

#define BIGF  3.4e38f

typedef unsigned long long u64;

// ---------------- device scratch (static, no allocation) ----------------
__device__ int   g_nbr[N_ * K_];     // neighbor (src) global indices, sorted by distance
__device__ float g_h[N_ * H_];       // node features
__device__ float g_A[N_ * 64];       // per-node precomputed [h@W_hi | h@W_hj]

__device__ __forceinline__ float silu_f(float x) {
    return __fdividef(x, 1.0f + __expf(-x));
}

// ---------------- packed fp32x2 helpers (Blackwell dual-fp32 path) --------
__device__ __forceinline__ u64 pack2(float lo, float hi) {
    u64 r; asm("mov.b64 %0, {%1, %2};" : "=l"(r) : "f"(lo), "f"(hi)); return r;
}
__device__ __forceinline__ float2 unpk(u64 v) {
    float2 r; asm("mov.b64 {%0, %1}, %2;" : "=f"(r.x), "=f"(r.y) : "l"(v)); return r;
}
__device__ __forceinline__ u64 ffma2(u64 a, u64 b, u64 c) {
    u64 d; asm("fma.rn.f32x2 %0, %1, %2, %3;" : "=l"(d) : "l"(a), "l"(b), "l"(c)); return d;
}
__device__ __forceinline__ u64 fadd2(u64 a, u64 b) {
    u64 d; asm("add.rn.f32x2 %0, %1, %2;" : "=l"(d) : "l"(a), "l"(b)); return d;
}
__device__ __forceinline__ u64 fmul2(u64 a, u64 b) {
    u64 d; asm("mul.rn.f32x2 %0, %1, %2;" : "=l"(d) : "l"(a), "l"(b)); return d;
}

// Branchless sorted insert with index payload.
__device__ __forceinline__ void insert20(float (&av)[K_], int (&ai)[K_], float d, int j) {
#pragma unroll
    for (int s = K_ - 1; s >= 1; s--) {
        bool c1 = d < av[s];
        bool c2 = d < av[s - 1];
        float nv = c1 ? (c2 ? av[s - 1] : d) : av[s];
        int   ni = c1 ? (c2 ? ai[s - 1] : j) : ai[s];
        av[s] = nv; ai[s] = ni;
    }
    bool c = d < av[0];
    av[0] = c ? d : av[0];
    ai[0] = c ? j : ai[0];
}

// ======================= kNN (exact top-20 per node) =======================
// Packed distance eval: 2 candidates per iteration via f32x2.
__global__ __launch_bounds__(256) void knn_kernel(const float* __restrict__ pos) {
    __shared__ ulonglong2 sxy[NPG_ / 2];   // (x-pair, y-pair)
    __shared__ ulonglong2 szq[NPG_ / 2];   // (z-pair, |p|^2-pair)
    const int graph = blockIdx.x >> 2;
    const int base  = graph * NPG_;
    for (int j2 = threadIdx.x; j2 < NPG_ / 2; j2 += 256) {
        int j0 = 2 * j2;
        float x0 = pos[(base + j0) * 3 + 0], y0 = pos[(base + j0) * 3 + 1], z0 = pos[(base + j0) * 3 + 2];
        float x1 = pos[(base + j0 + 1) * 3 + 0], y1 = pos[(base + j0 + 1) * 3 + 1], z1 = pos[(base + j0 + 1) * 3 + 2];
        float q0 = fmaf(x0, x0, fmaf(y0, y0, z0 * z0));
        float q1 = fmaf(x1, x1, fmaf(y1, y1, z1 * z1));
        ulonglong2 a; a.x = pack2(x0, x1); a.y = pack2(y0, y1); sxy[j2] = a;
        ulonglong2 b; b.x = pack2(z0, z1); b.y = pack2(q0, q1); szq[j2] = b;
    }
    __syncthreads();

    const int il = ((blockIdx.x & 3) << 8) + threadIdx.x;
    const float xi = pos[(base + il) * 3 + 0];
    const float yi = pos[(base + il) * 3 + 1];
    const float zi = pos[(base + il) * 3 + 2];
    const float sqi = fmaf(xi, xi, fmaf(yi, yi, zi * zi));
    const u64 pxi = pack2(xi, xi), pyi = pack2(yi, yi), pzi = pack2(zi, zi);
    const u64 psq = pack2(sqi, sqi), pm2 = pack2(-2.0f, -2.0f);

    float av[K_]; int ai[K_];
#pragma unroll
    for (int s = 0; s < K_; s++) { av[s] = BIGF; ai[s] = 0; }

    float bd0 = 0, bd1 = 0, bd2 = 0, bd3 = 0;
    int   bj0 = 0, bj1 = 0, bj2 = 0, bj3 = 0;
    int   cnt = 0;

#define KNN_FLUSH() do {                                               \
        float f0 = (cnt > 0) ? bd0 : BIGF;                             \
        float f1 = (cnt > 1) ? bd1 : BIGF;                             \
        float f2 = (cnt > 2) ? bd2 : BIGF;                             \
        float f3 = (cnt > 3) ? bd3 : BIGF;                             \
        insert20(av, ai, f0, bj0);                                     \
        insert20(av, ai, f1, bj1);                                     \
        insert20(av, ai, f2, bj2);                                     \
        insert20(av, ai, f3, bj3);                                     \
        cnt = 0;                                                       \
    } while (0)

#define KNN_PUSH(dd, jj) do {                                          \
        bd0 = (cnt == 0) ? (dd) : bd0;  bj0 = (cnt == 0) ? (jj) : bj0; \
        bd1 = (cnt == 1) ? (dd) : bd1;  bj1 = (cnt == 1) ? (jj) : bj1; \
        bd2 = (cnt == 2) ? (dd) : bd2;  bj2 = (cnt == 2) ? (jj) : bj2; \
        bd3 = (cnt == 3) ? (dd) : bd3;  bj3 = (cnt == 3) ? (jj) : bj3; \
        cnt++;                                                         \
    } while (0)

    for (int j2 = 0; j2 < NPG_ / 2; j2++) {
        ulonglong2 a = sxy[j2];
        ulonglong2 b = szq[j2];
        u64 dot = ffma2(pxi, a.x, ffma2(pyi, a.y, fmul2(pzi, b.x)));
        u64 dp  = ffma2(pm2, dot, fadd2(psq, b.y));
        float2 d = unpk(dp);
        int j0 = 2 * j2;
        float d0 = (j0     == il) ? BIGF : d.x;
        float d1 = (j0 + 1 == il) ? BIGF : d.y;
        if (d0 < av[K_ - 1]) KNN_PUSH(d0, j0);
        if (d1 < av[K_ - 1]) KNN_PUSH(d1, j0 + 1);
        // buffer has depth 4; flush at >=3 so next iter's 2 pushes can't overflow
        if (__any_sync(0xffffffffu, cnt >= 3)) KNN_FLUSH();
    }
    KNN_FLUSH();

    const int ob = (base + il) * K_;
#pragma unroll
    for (int s = 0; s < K_; s++) g_nbr[ob + s] = base + ai[s];
}

// ======================= node embedding + A(layer 0) =======================
__global__ __launch_bounds__(256) void embed_kernel(
    const float* __restrict__ pos,
    const float* __restrict__ pw1, const float* __restrict__ pb1,
    const float* __restrict__ pw2, const float* __restrict__ pb2,
    const float* __restrict__ ew1)
{
    __shared__ float w1[48], b1[16], w2[256], b2[16], wA[1024];
    const int tid = threadIdx.x;
    if (tid < 48)  w1[tid] = pw1[tid];
    if (tid < 16)  b1[tid] = pb1[tid];
    for (int q = tid; q < 256; q += 256) w2[q] = pw2[q];
    if (tid >= 32 && tid < 48) b2[tid - 32] = pb2[tid - 32];
    for (int q = tid; q < 1024; q += 256) wA[q] = ew1[q];
    __syncthreads();

    const int n = blockIdx.x * 256 + tid;
    const float p0 = pos[n * 3 + 0], p1 = pos[n * 3 + 1], p2 = pos[n * 3 + 2];

    float t[16];
#pragma unroll
    for (int o = 0; o < 16; o++)
        t[o] = silu_f(fmaf(p2, w1[32 + o], fmaf(p1, w1[16 + o], fmaf(p0, w1[o], b1[o]))));

    float h[16];
#pragma unroll
    for (int o = 0; o < 16; o++) {
        float hv = b2[o];
#pragma unroll
        for (int q = 0; q < 16; q++) hv = fmaf(t[q], w2[q * 16 + o], hv);
        h[o] = hv;
        g_h[n * 16 + o] = hv;
    }

    // A[n] = h @ ew1[0][0:32,:]  (packed f32x2)
    u64 ph[16];
#pragma unroll
    for (int q = 0; q < 16; q++) ph[q] = pack2(h[q], h[q]);
#pragma unroll
    for (int part = 0; part < 2; part++) {
#pragma unroll
        for (int og = 0; og < 4; og++) {
            u64 a0 = 0, a1 = 0, a2 = 0, a3 = 0;
            const float* Wb = wA + part * 512 + og * 8;
#pragma unroll
            for (int q = 0; q < 16; q++) {
                const ulonglong2* wr = (const ulonglong2*)(Wb + q * 32);
                ulonglong2 wlo = wr[0], whi = wr[1];
                a0 = ffma2(ph[q], wlo.x, a0); a1 = ffma2(ph[q], wlo.y, a1);
                a2 = ffma2(ph[q], whi.x, a2); a3 = ffma2(ph[q], whi.y, a3);
            }
            ulonglong2* dst = (ulonglong2*)(g_A + n * 64 + part * 32 + og * 8);
            ulonglong2 o0; o0.x = a0; o0.y = a1;
            ulonglong2 o1; o1.x = a2; o1.y = a3;
            dst[0] = o0; dst[1] = o1;
        }
    }
}

// ======================= fused layer kernel ================================
// 32 nodes/block, 320 threads, two edges per thread, packed f32x2 math.
#define SM_WG   0       // 5x32 geo rows of ew1
#define SM_B1   160
#define SM_W2   192     // 32x16
#define SM_B2   704
#define SM_W3   720     // 16x16
#define SM_B3   976
#define SM_N1   992     // 48x32 (reused for next-layer ew1[0:1024] in epilogue)
#define SM_NB1  2528
#define SM_N2   2560    // 32x16
#define SM_NB2  3072
#define SM_OW1  3088    // 16x16
#define SM_OB1  3344
#define SM_OW2  3360    // 16x8
#define SM_OB2  3488
#define SM_OW3  3496    // 8x3
#define SM_OB3  3520
#define SM_M    3536    // 32 nodes x 20 edges x 20 floats (16 used + pad)
#define SM_CAT  16336   // 32 x 48
#define SM_T1   17872   // 32 x 32
#define SM_HN   18896   // 32 x 16
#define SMEM_FLOATS 19408
#define SMEM_BYTES  (SMEM_FLOATS * 4)

__global__ __launch_bounds__(320, 2) void layer_kernel(
    const float* __restrict__ pos,
    const float* __restrict__ ew1, const float* __restrict__ eb1,
    const float* __restrict__ ew2, const float* __restrict__ eb2,
    const float* __restrict__ ew3, const float* __restrict__ eb3,
    const float* __restrict__ nw1, const float* __restrict__ nb1,
    const float* __restrict__ nw2, const float* __restrict__ nb2,
    const float* __restrict__ ow1, const float* __restrict__ ob1,
    const float* __restrict__ ow2, const float* __restrict__ ob2,
    const float* __restrict__ ow3, const float* __restrict__ ob3,
    float* __restrict__ out, int l, int is_last)
{
    extern __shared__ float S[];
    const int tid = threadIdx.x;

    for (int q = tid; q < 160;  q += 320) S[SM_WG  + q] = ew1[l * 1184 + 1024 + q];
    for (int q = tid; q < 32;   q += 320) S[SM_B1  + q] = eb1[l * 32  + q];
    for (int q = tid; q < 512;  q += 320) S[SM_W2  + q] = ew2[l * 512 + q];
    for (int q = tid; q < 16;   q += 320) S[SM_B2  + q] = eb2[l * 16  + q];
    for (int q = tid; q < 256;  q += 320) S[SM_W3  + q] = ew3[l * 256 + q];
    for (int q = tid; q < 16;   q += 320) S[SM_B3  + q] = eb3[l * 16  + q];
    for (int q = tid; q < 1536; q += 320) S[SM_N1  + q] = nw1[l * 1536 + q];
    for (int q = tid; q < 32;   q += 320) S[SM_NB1 + q] = nb1[l * 32  + q];
    for (int q = tid; q < 512;  q += 320) S[SM_N2  + q] = nw2[l * 512 + q];
    for (int q = tid; q < 16;   q += 320) S[SM_NB2 + q] = nb2[l * 16  + q];
    if (is_last) {
        for (int q = tid; q < 256; q += 320) S[SM_OW1 + q] = ow1[q];
        for (int q = tid; q < 16;  q += 320) S[SM_OB1 + q] = ob1[q];
        for (int q = tid; q < 128; q += 320) S[SM_OW2 + q] = ow2[q];
        for (int q = tid; q < 8;   q += 320) S[SM_OB2 + q] = ob2[q];
        for (int q = tid; q < 24;  q += 320) S[SM_OW3 + q] = ow3[q];
        for (int q = tid; q < 3;   q += 320) S[SM_OB3 + q] = ob3[q];
    }
    __syncthreads();

    // ---------------- edge phase: two edges per thread, packed math --------
    {
        const int nl   = tid / 10;
        const int k0   = tid - nl * 10;
        const int node = blockIdx.x * 32 + nl;
        const int src0 = g_nbr[node * K_ + k0];
        const int src1 = g_nbr[node * K_ + k0 + 10];

        const float pix = pos[node * 3 + 0], piy = pos[node * 3 + 1], piz = pos[node * 3 + 2];
        const float ni2 = sqrtf(fmaf(pix, pix, fmaf(piy, piy, piz * piz)));
        const float ii  = __fdividef(1.0f, ni2 + 1e-8f);
        const float uix = pix * ii, uiy = piy * ii, uiz = piz * ii;

        float geo0[5], geo1[5];
        {
            const float pjx = pos[src0 * 3 + 0], pjy = pos[src0 * 3 + 1], pjz = pos[src0 * 3 + 2];
            const float rx = pjx - pix, ry = pjy - piy, rz = pjz - piz;
            const float dist = sqrtf(fmaf(rx, rx, fmaf(ry, ry, rz * rz)));
            const float inv  = __fdividef(1.0f, dist + 1e-8f);
            const float nj2  = sqrtf(fmaf(pjx, pjx, fmaf(pjy, pjy, pjz * pjz)));
            const float ij   = __fdividef(1.0f, nj2 + 1e-8f);
            geo0[0] = dist; geo0[1] = rx * inv; geo0[2] = ry * inv; geo0[3] = rz * inv;
            geo0[4] = uix * (pjx * ij) + uiy * (pjy * ij) + uiz * (pjz * ij);
        }
        {
            const float pjx = pos[src1 * 3 + 0], pjy = pos[src1 * 3 + 1], pjz = pos[src1 * 3 + 2];
            const float rx = pjx - pix, ry = pjy - piy, rz = pjz - piz;
            const float dist = sqrtf(fmaf(rx, rx, fmaf(ry, ry, rz * rz)));
            const float inv  = __fdividef(1.0f, dist + 1e-8f);
            const float nj2  = sqrtf(fmaf(pjx, pjx, fmaf(pjy, pjy, pjz * pjz)));
            const float ij   = __fdividef(1.0f, nj2 + 1e-8f);
            geo1[0] = dist; geo1[1] = rx * inv; geo1[2] = ry * inv; geo1[3] = rz * inv;
            geo1[4] = uix * (pjx * ij) + uiy * (pjy * ij) + uiz * (pjz * ij);
        }
        u64 pg0[5], pg1[5];
#pragma unroll
        for (int g = 0; g < 5; g++) { pg0[g] = pack2(geo0[g], geo0[g]); pg1[g] = pack2(geo1[g], geo1[g]); }

        u64 m20[8], m21[8];
#pragma unroll
        for (int q4 = 0; q4 < 4; q4++) {
            ulonglong2 b = *(const ulonglong2*)(S + SM_B2 + q4 * 4);
            m20[q4 * 2] = b.x; m20[q4 * 2 + 1] = b.y;
            m21[q4 * 2] = b.x; m21[q4 * 2 + 1] = b.y;
        }

#pragma unroll
        for (int c = 0; c < 2; c++) {
            u64 t0[8], t1[8];
            const ulonglong2* Ai  = (const ulonglong2*)(g_A + node * 64 + c * 16);
            const ulonglong2* Aj0 = (const ulonglong2*)(g_A + src0 * 64 + 32 + c * 16);
            const ulonglong2* Aj1 = (const ulonglong2*)(g_A + src1 * 64 + 32 + c * 16);
#pragma unroll
            for (int q4 = 0; q4 < 4; q4++) {
                ulonglong2 ai = Ai[q4], b0 = Aj0[q4], b1 = Aj1[q4];
                ulonglong2 bb = *(const ulonglong2*)(S + SM_B1 + c * 16 + q4 * 4);
                u64 basex = fadd2(ai.x, bb.x);
                u64 basey = fadd2(ai.y, bb.y);
                t0[q4 * 2]     = fadd2(basex, b0.x);
                t0[q4 * 2 + 1] = fadd2(basey, b0.y);
                t1[q4 * 2]     = fadd2(basex, b1.x);
                t1[q4 * 2 + 1] = fadd2(basey, b1.y);
            }
#pragma unroll
            for (int g = 0; g < 5; g++) {
#pragma unroll
                for (int q4 = 0; q4 < 4; q4++) {
                    ulonglong2 w = *(const ulonglong2*)(S + SM_WG + g * 32 + c * 16 + q4 * 4);
                    t0[q4 * 2]     = ffma2(pg0[g], w.x, t0[q4 * 2]);
                    t0[q4 * 2 + 1] = ffma2(pg0[g], w.y, t0[q4 * 2 + 1]);
                    t1[q4 * 2]     = ffma2(pg1[g], w.x, t1[q4 * 2]);
                    t1[q4 * 2 + 1] = ffma2(pg1[g], w.y, t1[q4 * 2 + 1]);
                }
            }
            // silu + W2 accumulate (rows c*16+2q, c*16+2q+1)
#pragma unroll
            for (int q = 0; q < 8; q++) {
                float2 v0 = unpk(t0[q]), v1 = unpk(t1[q]);
                float s00 = silu_f(v0.x), s01 = silu_f(v0.y);
                float s10 = silu_f(v1.x), s11 = silu_f(v1.y);
                u64 p00 = pack2(s00, s00), p01 = pack2(s01, s01);
                u64 p10 = pack2(s10, s10), p11 = pack2(s11, s11);
                const int r0 = (c * 16 + q * 2) * 16;
                const int r1 = r0 + 16;
#pragma unroll
                for (int qq = 0; qq < 4; qq++) {
                    ulonglong2 wa = *(const ulonglong2*)(S + SM_W2 + r0 + qq * 4);
                    ulonglong2 wb = *(const ulonglong2*)(S + SM_W2 + r1 + qq * 4);
                    m20[qq * 2]     = ffma2(p00, wa.x, m20[qq * 2]);
                    m20[qq * 2 + 1] = ffma2(p00, wa.y, m20[qq * 2 + 1]);
                    m20[qq * 2]     = ffma2(p01, wb.x, m20[qq * 2]);
                    m20[qq * 2 + 1] = ffma2(p01, wb.y, m20[qq * 2 + 1]);
                    m21[qq * 2]     = ffma2(p10, wa.x, m21[qq * 2]);
                    m21[qq * 2 + 1] = ffma2(p10, wa.y, m21[qq * 2 + 1]);
                    m21[qq * 2]     = ffma2(p11, wb.x, m21[qq * 2]);
                    m21[qq * 2 + 1] = ffma2(p11, wb.y, m21[qq * 2 + 1]);
                }
            }
        }

        // layer 3: silu(m2) @ W3 + b3
        u64 mv0[8], mv1[8];
#pragma unroll
        for (int q4 = 0; q4 < 4; q4++) {
            ulonglong2 b = *(const ulonglong2*)(S + SM_B3 + q4 * 4);
            mv0[q4 * 2] = b.x; mv0[q4 * 2 + 1] = b.y;
            mv1[q4 * 2] = b.x; mv1[q4 * 2 + 1] = b.y;
        }
#pragma unroll
        for (int q = 0; q < 8; q++) {
            float2 v0 = unpk(m20[q]), v1 = unpk(m21[q]);
            float s00 = silu_f(v0.x), s01 = silu_f(v0.y);
            float s10 = silu_f(v1.x), s11 = silu_f(v1.y);
            u64 p00 = pack2(s00, s00), p01 = pack2(s01, s01);
            u64 p10 = pack2(s10, s10), p11 = pack2(s11, s11);
            const int r0 = (q * 2) * 16;
            const int r1 = r0 + 16;
#pragma unroll
            for (int qq = 0; qq < 4; qq++) {
                ulonglong2 wa = *(const ulonglong2*)(S + SM_W3 + r0 + qq * 4);
                ulonglong2 wb = *(const ulonglong2*)(S + SM_W3 + r1 + qq * 4);
                mv0[qq * 2]     = ffma2(p00, wa.x, mv0[qq * 2]);
                mv0[qq * 2 + 1] = ffma2(p00, wa.y, mv0[qq * 2 + 1]);
                mv0[qq * 2]     = ffma2(p01, wb.x, mv0[qq * 2]);
                mv0[qq * 2 + 1] = ffma2(p01, wb.y, mv0[qq * 2 + 1]);
                mv1[qq * 2]     = ffma2(p10, wa.x, mv1[qq * 2]);
                mv1[qq * 2 + 1] = ffma2(p10, wa.y, mv1[qq * 2 + 1]);
                mv1[qq * 2]     = ffma2(p11, wb.x, mv1[qq * 2]);
                mv1[qq * 2 + 1] = ffma2(p11, wb.y, mv1[qq * 2 + 1]);
            }
        }
        ulonglong2* M0 = (ulonglong2*)(S + SM_M + (nl * 20 + k0) * 20);
        ulonglong2* M1 = (ulonglong2*)(S + SM_M + (nl * 20 + k0 + 10) * 20);
#pragma unroll
        for (int q4 = 0; q4 < 4; q4++) {
            ulonglong2 o0; o0.x = mv0[q4 * 2]; o0.y = mv0[q4 * 2 + 1];
            ulonglong2 o1; o1.x = mv1[q4 * 2]; o1.y = mv1[q4 * 2 + 1];
            M0[q4] = o0; M1[q4] = o1;
        }
    }
    __syncthreads();

    // ---------------- reduce: mean & max over 20 edges ----------------
    if (tid < 128) {
        const int nn = tid >> 2, d4 = tid & 3;
        float4 sum = make_float4(0.f, 0.f, 0.f, 0.f);
        float4 mx  = make_float4(-BIGF, -BIGF, -BIGF, -BIGF);
#pragma unroll
        for (int e = 0; e < 20; e++) {
            float4 v = *(const float4*)(S + SM_M + (nn * 20 + e) * 20 + d4 * 4);
            sum.x += v.x; sum.y += v.y; sum.z += v.z; sum.w += v.w;
            mx.x = fmaxf(mx.x, v.x); mx.y = fmaxf(mx.y, v.y);
            mx.z = fmaxf(mx.z, v.z); mx.w = fmaxf(mx.w, v.w);
        }
        float4 hv = *(const float4*)(g_h + (blockIdx.x * 32 + nn) * 16 + d4 * 4);
        *(float4*)(S + SM_CAT + nn * 48 + d4 * 4)      = hv;
        *(float4*)(S + SM_CAT + nn * 48 + 16 + d4 * 4) =
            make_float4(sum.x * 0.05f, sum.y * 0.05f, sum.z * 0.05f, sum.w * 0.05f);
        *(float4*)(S + SM_CAT + nn * 48 + 32 + d4 * 4) = mx;
    }
    __syncthreads();

    // ---------------- node MLP 1: 48 -> 32 (packed, 4 outputs/thread) ------
    if (tid < 256) {
        const int nn = tid >> 3, o4 = tid & 7;
        ulonglong2 bb = *(const ulonglong2*)(S + SM_NB1 + o4 * 4);
        u64 a0 = bb.x, a1 = bb.y;
#pragma unroll
        for (int q = 0; q < 48; q++) {
            float cv = S[SM_CAT + nn * 48 + q];
            u64 pc = pack2(cv, cv);
            ulonglong2 w = *(const ulonglong2*)(S + SM_N1 + q * 32 + o4 * 4);
            a0 = ffma2(pc, w.x, a0); a1 = ffma2(pc, w.y, a1);
        }
        float2 f0 = unpk(a0), f1 = unpk(a1);
        *(float4*)(S + SM_T1 + nn * 32 + o4 * 4) =
            make_float4(silu_f(f0.x), silu_f(f0.y), silu_f(f1.x), silu_f(f1.y));
    }
    __syncthreads();

    // ---------------- node MLP 2 + residual ----------------
    if (tid < 128) {
        const int nn = tid >> 2, dg = tid & 3;
        ulonglong2 bb = *(const ulonglong2*)(S + SM_NB2 + dg * 4);
        u64 a0 = bb.x, a1 = bb.y;
#pragma unroll
        for (int q = 0; q < 32; q++) {
            float tv = S[SM_T1 + nn * 32 + q];
            u64 pt = pack2(tv, tv);
            ulonglong2 w = *(const ulonglong2*)(S + SM_N2 + q * 16 + dg * 4);
            a0 = ffma2(pt, w.x, a0); a1 = ffma2(pt, w.y, a1);
        }
        ulonglong2 h0 = *(const ulonglong2*)(S + SM_CAT + nn * 48 + dg * 4);
        ulonglong2 hv; hv.x = fadd2(h0.x, a0); hv.y = fadd2(h0.y, a1);
        *(ulonglong2*)(S + SM_HN + nn * 16 + dg * 4) = hv;
        *(ulonglong2*)(g_h + (blockIdx.x * 32 + nn) * 16 + dg * 4) = hv;
    }

    if (is_last) {
        __syncthreads();
        // ---------------- output head ----------------
        for (int idx = tid; idx < 512; idx += 320) {
            const int nn = idx >> 4, d = idx & 15;
            float a1 = S[SM_OB1 + d];
#pragma unroll
            for (int q = 0; q < 16; q++) a1 = fmaf(S[SM_HN + nn * 16 + q], S[SM_OW1 + q * 16 + d], a1);
            S[SM_T1 + nn * 16 + d] = silu_f(a1);
        }
        __syncthreads();
        if (tid < 256) {
            const int nn = tid >> 3, d = tid & 7;
            float a1 = S[SM_OB2 + d];
#pragma unroll
            for (int q = 0; q < 16; q++) a1 = fmaf(S[SM_T1 + nn * 16 + q], S[SM_OW2 + q * 8 + d], a1);
            S[SM_CAT + nn * 8 + d] = silu_f(a1);
        }
        __syncthreads();
        if (tid < 96) {
            const int nn = tid / 3, d = tid - nn * 3;
            float a1 = S[SM_OB3 + d];
#pragma unroll
            for (int q = 0; q < 8; q++) a1 = fmaf(S[SM_CAT + nn * 8 + q], S[SM_OW3 + q * 3 + d], a1);
            out[(blockIdx.x * 32 + nn) * 3 + d] = a1;
        }
        return;
    }

    // ---------------- epilogue: A_{l+1}[node] = h_new @ ew1[l+1][0:32,:] ---
    __syncthreads();
    for (int q = tid; q < 1024; q += 320) S[SM_N1 + q] = ew1[(l + 1) * 1184 + q];
    __syncthreads();
    if (tid < 256) {
        const int nn  = tid >> 3;       // node 0..31
        const int o8  = tid & 7;        // output octet 0..7 (8 floats each)
        const int isJ = o8 >> 2;        // 0: Ai half, 1: Aj half
        const int col0 = (o8 & 3) * 8;
        const float* Wb = S + SM_N1 + isJ * 512 + col0;
        u64 a0 = 0, a1 = 0, a2 = 0, a3 = 0;
#pragma unroll
        for (int q = 0; q < 16; q++) {
            float hv = S[SM_HN + nn * 16 + q];
            u64 ph = pack2(hv, hv);
            const ulonglong2* wr = (const ulonglong2*)(Wb + q * 32);
            ulonglong2 wlo = wr[0], whi = wr[1];
            a0 = ffma2(ph, wlo.x, a0); a1 = ffma2(ph, wlo.y, a1);
            a2 = ffma2(ph, whi.x, a2); a3 = ffma2(ph, whi.y, a3);
        }
        ulonglong2* dst = (ulonglong2*)(g_A + (blockIdx.x * 32 + nn) * 64 + o8 * 8);
        ulonglong2 o0; o0.x = a0; o0.y = a1;
        ulonglong2 o1; o1.x = a2; o1.y = a3;
        dst[0] = o0; dst[1] = o1;
    }
}

// ======================= launch ============================================
extern "C" void kernel_launch(void* const* d_in, const int* in_sizes, int n_in,
                              void* d_out, int out_size) {
    (void)in_sizes; (void)n_in; (void)out_size;
    const float* pos = (const float*)d_in[0];
    const float* pw1 = (const float*)d_in[1];
    const float* pb1 = (const float*)d_in[2];
    const float* pw2 = (const float*)d_in[3];
    const float* pb2 = (const float*)d_in[4];
    const float* ew1 = (const float*)d_in[5];
    const float* eb1 = (const float*)d_in[6];
    const float* ew2 = (const float*)d_in[7];
    const float* eb2 = (const float*)d_in[8];
    const float* ew3 = (const float*)d_in[9];
    const float* eb3 = (const float*)d_in[10];
    const float* nw1 = (const float*)d_in[11];
    const float* nb1 = (const float*)d_in[12];
    const float* nw2 = (const float*)d_in[13];
    const float* nb2 = (const float*)d_in[14];
    const float* ow1 = (const float*)d_in[15];
    const float* ob1 = (const float*)d_in[16];
    const float* ow2 = (const float*)d_in[17];
    const float* ob2 = (const float*)d_in[18];
    const float* ow3 = (const float*)d_in[19];
    const float* ob3 = (const float*)d_in[20];
    float* out = (float*)d_out;

    cudaFuncSetAttribute(layer_kernel, cudaFuncAttributeMaxDynamicSharedMemorySize, SMEM_BYTES);

    knn_kernel<<<N_ / 256, 256>>>(pos);
    embed_kernel<<<N_ / 256, 256>>>(pos, pw1, pb1, pw2, pb2, ew1);
    for (int l = 0; l < L_; l++) {
        layer_kernel<<<N_ / 32, 320, SMEM_BYTES>>>(
            pos, ew1, eb1, ew2, eb2, ew3, eb3,
            nw1, nb1, nw2, nb2,
            ow1, ob1, ow2, ob2, ow3, ob3,
            out, l, (l == L_ - 1) ? 1 : 0);
    }
}